// round 11
// baseline (speedup 1.0000x reference)
#include <cuda_runtime.h>
#include <cuda_fp16.h>
#include <math.h>

#define Bb   512
#define Hh   256
#define Ld   256
#define Tt   64
#define Vv   128
#define NL   2
#define G    4
#define NTH  512

// ---------------- packed fp16 weights ----------------
// attn-h / comb-a: P[(k4*256 + j)*4 + c] = W[j][off + k4*4 + c], thread-half k-split.
// GRU (per layer, per type): slot layout P[(k4*1536 + s)*4 + c] = W[n][kh*128 + k4*4 + c]
//   with n = s % 768, kh = s / 768, k4 in 0..31.
// out: P[(k4*128 + j)*4 + c] = W[j][k4*4 + c].
#define OFF_ATTNH 0         // 65536
#define OFF_COMBA 65536     // 65536
#define OFF_GIH   131072    // 2 x 196608
#define OFF_GHH   524288    // 2 x 196608
#define OFF_OUT   917504    // 32768
#define PACK_TOTAL 950272

#define PACK_BLOCKS 3712
#define ENC_BLOCKS  32768

__device__ __align__(16) __half g_pack[PACK_TOTAL];
__device__ __align__(16) __half g_enc[(size_t)Bb * Hh * Ld];
__device__ __align__(16) float  g_Tattn[Vv * Ld];   // emb@attn_w_e^T + attn_b
__device__ __align__(16) float  g_Tcomb[Vv * Hh];   // emb@comb_w_e^T + comb_b

__global__ void pack_all_kernel(const float* __restrict__ aw, const float* __restrict__ cw,
                                const float* __restrict__ gih, const float* __restrict__ ghh,
                                const float* __restrict__ ow, const float* __restrict__ x)
{
    if (blockIdx.x < PACK_BLOCKS) {
        int i = blockIdx.x * blockDim.x + threadIdx.x;
        if (i >= PACK_TOTAL) return;
        float v;
        if (i < 65536) {                        // attn h-part: W[j][256 + k]
            int c = i & 3, j = (i >> 2) & 255, k4 = i >> 10;
            v = aw[j * 512 + 256 + k4 * 4 + c];
        } else if (i < 131072) {                // comb applied-part: W[j][k]
            int r = i - 65536;
            int c = r & 3, j = (r >> 2) & 255, k4 = r >> 10;
            v = cw[j * 512 + k4 * 4 + c];
        } else if (i < 917504) {                // gru slot layout (ih then hh)
            int r = i - 131072;
            const float* W = (r < 393216) ? gih : ghh;
            int r2 = r % 393216;
            int layer = r2 / 196608;
            int q2 = r2 % 196608;
            int c  = q2 & 3;
            int q  = q2 >> 2;                   // k4*1536 + s
            int s  = q % 1536;
            int k4 = q / 1536;
            int n  = s % 768;
            int kh = s / 768;
            v = W[layer * 196608 + n * 256 + kh * 128 + k4 * 4 + c];
        } else {                                // out
            int r = i - 917504;
            int c = r & 3, j = (r >> 2) & 127, k4 = r >> 9;
            v = ow[j * 256 + k4 * 4 + c];
        }
        g_pack[i] = __float2half(v);
    } else {
        size_t i = (size_t)(blockIdx.x - PACK_BLOCKS) * blockDim.x + threadIdx.x;
        float4 v = ((const float4*)x)[i];
        __half2 h0 = __floats2half2_rn(v.x, v.y);
        __half2 h1 = __floats2half2_rn(v.z, v.w);
        uint2 o;
        o.x = *(unsigned*)&h0;
        o.y = *(unsigned*)&h1;
        ((uint2*)g_enc)[i] = o;
    }
}

__global__ void precompute_tok_kernel(const float* __restrict__ emb,
                                      const float* __restrict__ aw, const float* __restrict__ ab,
                                      const float* __restrict__ cw, const float* __restrict__ cb)
{
    __shared__ float se[Hh];
    int tok = blockIdx.x & 127;
    bool isComb = blockIdx.x >= 128;
    int j = threadIdx.x;
    se[j] = emb[tok * Hh + j];
    __syncthreads();
    const float* W = isComb ? (cw + j * 512 + 256) : (aw + j * 512);
    float s = 0.f;
    #pragma unroll 8
    for (int k = 0; k < 256; k++) s += W[k] * se[k];
    if (isComb) g_Tcomb[tok * Hh + j] = s + cb[j];
    else        g_Tattn[tok * Ld + j] = s + ab[j];
}

// ---------------- f32x2 helpers ----------------
typedef unsigned long long u64;

__device__ __forceinline__ void fma2(u64& d, u64 a, u64 b) {
    asm("fma.rn.f32x2 %0, %1, %2, %0;" : "+l"(d) : "l"(a), "l"(b));
}
__device__ __forceinline__ float sum2(u64 v) {
    return __uint_as_float((unsigned)v) + __uint_as_float((unsigned)(v >> 32));
}
__device__ __forceinline__ u64 cvt2(unsigned h) {
    float2 f = __half22float2(*(__half2*)&h);
    return ((u64)__float_as_uint(f.y) << 32) | (u64)__float_as_uint(f.x);
}

// ---------------- block reduce (4 values, 16 warps) ----------------
__device__ __forceinline__ void block_reduce4(float v[G], float* sm, int tid, bool is_max) {
    __syncthreads();
    #pragma unroll
    for (int g = 0; g < G; g++) {
        #pragma unroll
        for (int o = 16; o > 0; o >>= 1) {
            float oth = __shfl_xor_sync(0xffffffffu, v[g], o);
            v[g] = is_max ? fmaxf(v[g], oth) : (v[g] + oth);
        }
    }
    int wid = tid >> 5;
    if ((tid & 31) == 0) {
        #pragma unroll
        for (int g = 0; g < G; g++) sm[wid * G + g] = v[g];
    }
    __syncthreads();
    #pragma unroll
    for (int g = 0; g < G; g++) {
        float r = sm[g];
        #pragma unroll
        for (int w = 1; w < 16; w++)
            r = is_max ? fmaxf(r, sm[w * G + g]) : (r + sm[w * G + g]);
        v[g] = r;
    }
}

// slot matvec: 512 threads x 3 slots, K=256 split in two kh halves per slot map.
// dest[g*1536 + s] = dot(W_slot_s, vb[g][kh*128 .. kh*128+127])
__device__ __forceinline__ void slot_matvec(const __half* Wbase, const float* vb,
                                            float* dest, int tid, int kh1sel)
{
    u64 a0[G] = {0,0,0,0}, a1[G] = {0,0,0,0}, a2[G] = {0,0,0,0};
    const uint2* Wp = (const uint2*)Wbase + tid;
    #pragma unroll 4
    for (int k4 = 0; k4 < 32; k4++) {
        uint2 wa = Wp[k4 * 1536];
        uint2 wb = Wp[k4 * 1536 + 512];
        uint2 wc = Wp[k4 * 1536 + 1024];
        u64 wax = cvt2(wa.x), way = cvt2(wa.y);
        u64 wbx = cvt2(wb.x), wby = cvt2(wb.y);
        u64 wcx = cvt2(wc.x), wcy = cvt2(wc.y);
        #pragma unroll
        for (int g = 0; g < G; g++) {
            const ulonglong2* xp = (const ulonglong2*)(vb + g * Hh);
            ulonglong2 xa = xp[k4];        // kh=0 half
            ulonglong2 xb = xp[32 + k4];   // kh=1 half
            u64 x1x = kh1sel ? xb.x : xa.x;
            u64 x1y = kh1sel ? xb.y : xa.y;
            fma2(a0[g], wax, xa.x); fma2(a0[g], way, xa.y);
            fma2(a1[g], wbx, x1x);  fma2(a1[g], wby, x1y);
            fma2(a2[g], wcx, xb.x); fma2(a2[g], wcy, xb.y);
        }
    }
    #pragma unroll
    for (int g = 0; g < G; g++) {
        dest[g * 1536 + tid]        = sum2(a0[g]);
        dest[g * 1536 + tid + 512]  = sum2(a1[g]);
        dest[g * 1536 + tid + 1024] = sum2(a2[g]);
    }
}

// ---------------- dynamic smem layout (float offsets) ----------------
#define SO_H    0        // [2][4][256]  2048
#define SO_X    2048     // [4][256]     1024
#define SO_AW   3072     // 1024
#define SO_APP  4096     // 1024
#define SO_SCA  5120     // 1024
#define SO_SCB  6144     // 1024
#define SO_HHP  7168     // [2][4][1536] 12288
#define SO_IP   19456    // [4][1536]    6144
#define SO_OP   25600    // [4][4][128]  2048
#define SO_SOUT 27648    // [4][128][8]  4096
#define SO_RED  31744    // 64
#define SO_TOK  31808    // 4 ints
#define SMEM_FLOATS 31816
#define SMEM_BYTES (SMEM_FLOATS * 4)

// ---------------- main persistent decoder kernel ----------------
__global__ __launch_bounds__(NTH)
void decoder_kernel(const int*   __restrict__ y,      // [B,T]
                    const float* __restrict__ gbi,    // [2,768]
                    const float* __restrict__ gbh,    // [2,768]
                    const float* __restrict__ out_b,  // [V]
                    float* __restrict__ outp,         // [B,V,T]
                    float* __restrict__ attnp)        // [B,T,L]
{
    extern __shared__ __align__(16) float sm[];
    float* s_h   = sm + SO_H;
    float* s_x   = sm + SO_X;
    float* s_aw  = sm + SO_AW;
    float* s_app = sm + SO_APP;
    float* s_scA = sm + SO_SCA;
    float* s_scB = sm + SO_SCB;
    float* s_hhp = sm + SO_HHP;
    float* s_ip  = sm + SO_IP;
    float* s_op  = sm + SO_OP;
    float* s_out = sm + SO_SOUT;
    float* s_red = sm + SO_RED;
    int*   s_tok = (int*)(sm + SO_TOK);

    const int tid  = threadIdx.x;
    const int wid  = tid >> 5;
    const int lane = tid & 31;
    const int jj   = tid & 255;
    const bool hi  = (tid >= 256);
    const int kh1sel = hi ? 1 : 0;
    const int b0   = blockIdx.x * G;

    const __half* Pattnh = g_pack + OFF_ATTNH;
    const __half* Pcomba = g_pack + OFF_COMBA;
    const __half* Pgih   = g_pack + OFF_GIH;
    const __half* Pghh   = g_pack + OFF_GHH;
    const __half* Pout   = g_pack + OFF_OUT;

    // zero: hidden + pipelined partials (h=0 at t=0 => all zero is correct)
    for (int i = tid; i < SO_X; i += NTH)          s_h[i] = 0.f;            // s_h
    for (int i = tid; i < 2048; i += NTH) { s_scA[i] = 0.f; }               // scA+scB (contig)
    for (int i = tid; i < 12288; i += NTH)         s_hhp[i] = 0.f;
    __syncthreads();

    for (int t = 0; t < Tt; t++) {
        // -------- token fetch --------
        if (tid < G)
            s_tok[tid] = (t == 0) ? 0 : y[(b0 + tid) * Tt + t - 1];
        __syncthreads();

        // -------- softmax on pipelined scores (h-part precomputed last step) --------
        {
            float sc[G];
            #pragma unroll
            for (int g = 0; g < G; g++)
                sc[g] = hi ? -1e30f
                           : (s_scA[g * Ld + jj] + s_scB[g * Ld + jj]
                              + g_Tattn[s_tok[g] * Ld + jj]);
            float m[G];
            #pragma unroll
            for (int g = 0; g < G; g++) m[g] = sc[g];
            block_reduce4(m, s_red, tid, true);
            float p[G];
            #pragma unroll
            for (int g = 0; g < G; g++) p[g] = hi ? 0.f : __expf(sc[g] - m[g]);
            float s[G];
            #pragma unroll
            for (int g = 0; g < G; g++) s[g] = p[g];
            block_reduce4(s, s_red, tid, false);
            if (!hi) {
                #pragma unroll
                for (int g = 0; g < G; g++) {
                    float a = p[g] * (1.f / s[g]);
                    s_aw[g * Ld + jj] = a;
                    attnp[((size_t)(b0 + g) * Tt + t) * Ld + jj] = a;
                }
            }
            __syncthreads();
        }

        // -------- applied = aw @ enc (fp16 enc, warp owns fixed row g) --------
        {
            const int g = wid >> 2;
            const int hbase = (wid & 3) * 64;
            const float4* awp = (const float4*)(s_aw + g * Ld);
            const float4 A0 = awp[lane * 2];
            const float4 A1 = awp[lane * 2 + 1];
            const uint4* xrow =
                (const uint4*)(g_enc + ((size_t)(b0 + g) * Hh + hbase) * Ld) + lane;
            #pragma unroll
            for (int it = 0; it < 64; it += 8) {
                uint4 xv[8];
                #pragma unroll
                for (int u = 0; u < 8; u++) xv[u] = xrow[(it + u) * 32];
                float d[8];
                #pragma unroll
                for (int u = 0; u < 8; u++) {
                    float2 f0 = __half22float2(*(__half2*)&xv[u].x);
                    float2 f1 = __half22float2(*(__half2*)&xv[u].y);
                    float2 f2 = __half22float2(*(__half2*)&xv[u].z);
                    float2 f3 = __half22float2(*(__half2*)&xv[u].w);
                    d[u] = f0.x * A0.x + f0.y * A0.y + f1.x * A0.z + f1.y * A0.w
                         + f2.x * A1.x + f2.y * A1.y + f3.x * A1.z + f3.y * A1.w;
                }
                #pragma unroll
                for (int u = 0; u < 8; u++) {
                    #pragma unroll
                    for (int o = 16; o > 0; o >>= 1)
                        d[u] += __shfl_xor_sync(0xffffffffu, d[u], o);
                }
                if (lane == 0) {
                    #pragma unroll
                    for (int u = 0; u < 8; u++) s_app[g * Hh + hbase + it + u] = d[u];
                }
            }
        }
        __syncthreads();

        // -------- combine: applied-part lo/hi K-halves + token table --------
        {
            u64 acc[G] = {0, 0, 0, 0};
            const uint2* W = (const uint2*)Pcomba + (hi ? 32 * 256 : 0) + jj;
            const int kbase = hi ? 32 : 0;
            #pragma unroll 8
            for (int k4 = 0; k4 < 32; k4++) {
                uint2 wh = W[k4 * 256];
                u64 wx = cvt2(wh.x), wy = cvt2(wh.y);
                #pragma unroll
                for (int g = 0; g < G; g++) {
                    ulonglong2 xv = ((const ulonglong2*)(s_app + g * Hh))[kbase + k4];
                    fma2(acc[g], wx, xv.x);
                    fma2(acc[g], wy, xv.y);
                }
            }
            if (hi) {
                #pragma unroll
                for (int g = 0; g < G; g++) s_op[g * Hh + jj] = sum2(acc[g]); // scratch
            }
            __syncthreads();
            if (!hi) {
                #pragma unroll
                for (int g = 0; g < G; g++)
                    s_x[g * Hh + jj] = fmaxf(sum2(acc[g]) + s_op[g * Hh + jj]
                                             + g_Tcomb[s_tok[g] * Hh + jj], 0.f);
            }
            __syncthreads();
        }

        // -------- GRU layers: ih slot matvec (all 512 threads) + combine --------
        #pragma unroll
        for (int l = 0; l < NL; l++) {
            slot_matvec(Pgih + l * 196608, s_x, s_ip, tid, kh1sel);
            __syncthreads();
            if (!hi) {
                const float* hp = s_hhp + l * G * 1536;
                const float bi0 = gbi[l * 768 + jj];
                const float bi1 = gbi[l * 768 + 256 + jj];
                const float bi2 = gbi[l * 768 + 512 + jj];
                const float bh0 = gbh[l * 768 + jj];
                const float bh1 = gbh[l * 768 + 256 + jj];
                const float bh2 = gbh[l * 768 + 512 + jj];
                #pragma unroll
                for (int g = 0; g < G; g++) {
                    float hprev = s_h[(l * G + g) * Hh + jj];
                    float i0 = s_ip[g*1536 + jj]        + s_ip[g*1536 + 768 + jj]  + bi0;
                    float i1 = s_ip[g*1536 + 256 + jj]  + s_ip[g*1536 + 1024 + jj] + bi1;
                    float i2 = s_ip[g*1536 + 512 + jj]  + s_ip[g*1536 + 1280 + jj] + bi2;
                    float h0 = hp[g*1536 + jj]          + hp[g*1536 + 768 + jj]    + bh0;
                    float h1 = hp[g*1536 + 256 + jj]    + hp[g*1536 + 1024 + jj]   + bh1;
                    float h2 = hp[g*1536 + 512 + jj]    + hp[g*1536 + 1280 + jj]   + bh2;
                    float r = 1.f / (1.f + __expf(-(i0 + h0)));
                    float z = 1.f / (1.f + __expf(-(i1 + h1)));
                    float n = tanhf(i2 + r * h2);
                    float hn = (1.f - z) * n + z * hprev;
                    s_h[(l * G + g) * Hh + jj] = hn;
                    s_x[g * Hh + jj]           = hn;
                }
            }
            __syncthreads();
        }

        // -------- MEGA phase (barrier-free): out(t) + attn-h(t+1) + hh(t+1) --------
        {
            // out projection: K split 4 ways across all threads
            int j  = tid & 127;
            int sl = tid >> 7;
            u64 acc[G] = {0, 0, 0, 0};
            const uint2* W = (const uint2*)Pout + j;
            #pragma unroll 8
            for (int k4 = sl * 16; k4 < sl * 16 + 16; k4++) {
                uint2 wh = W[k4 * 128];
                u64 wx = cvt2(wh.x), wy = cvt2(wh.y);
                #pragma unroll
                for (int g = 0; g < G; g++) {
                    ulonglong2 hv = ((const ulonglong2*)(s_x + g * Hh))[k4];
                    fma2(acc[g], wx, hv.x);
                    fma2(acc[g], wy, hv.y);
                }
            }
            #pragma unroll
            for (int g = 0; g < G; g++) s_op[(g * 4 + sl) * 128 + j] = sum2(acc[g]);

            if (t < Tt - 1) {
                // attn h-part for t+1 (lo/hi K-halves, raw partials)
                u64 aacc[G] = {0, 0, 0, 0};
                const uint2* Wa = (const uint2*)Pattnh + (hi ? 32 * 256 : 0) + jj;
                const int kbase = hi ? 32 : 0;
                #pragma unroll 8
                for (int k4 = 0; k4 < 32; k4++) {
                    uint2 wh = Wa[k4 * 256];
                    u64 wx = cvt2(wh.x), wy = cvt2(wh.y);
                    #pragma unroll
                    for (int g = 0; g < G; g++) {
                        ulonglong2 xv = ((const ulonglong2*)(s_h + g * Hh))[kbase + k4];
                        fma2(aacc[g], wx, xv.x);
                        fma2(aacc[g], wy, xv.y);
                    }
                }
                float* dstA = hi ? s_scB : s_scA;
                #pragma unroll
                for (int g = 0; g < G; g++) dstA[g * Ld + jj] = sum2(aacc[g]);

                // hh matvecs for t+1 (slot layout)
                slot_matvec(Pghh,          s_h,              s_hhp,            tid, kh1sel);
                slot_matvec(Pghh + 196608, s_h + G * Hh,     s_hhp + G * 1536, tid, kh1sel);
            }
        }
        __syncthreads();

        // -------- out finalize + log_softmax --------
        {
            int j = tid & 127;
            float oacc[G];
            #pragma unroll
            for (int g = 0; g < G; g++) {
                oacc[g] = (tid < 128)
                    ? (out_b[j] + s_op[(g * 4 + 0) * 128 + j] + s_op[(g * 4 + 1) * 128 + j]
                               + s_op[(g * 4 + 2) * 128 + j] + s_op[(g * 4 + 3) * 128 + j])
                    : -1e30f;
            }
            float m[G];
            #pragma unroll
            for (int g = 0; g < G; g++) m[g] = oacc[g];
            block_reduce4(m, s_red, tid, true);
            float p[G];
            #pragma unroll
            for (int g = 0; g < G; g++) p[g] = (tid < 128) ? __expf(oacc[g] - m[g]) : 0.f;
            float s[G];
            #pragma unroll
            for (int g = 0; g < G; g++) s[g] = p[g];
            block_reduce4(s, s_red, tid, false);
            if (tid < 128) {
                #pragma unroll
                for (int g = 0; g < G; g++)
                    s_out[(g * Vv + j) * 8 + (t & 7)] = oacc[g] - m[g] - logf(s[g]);
            }
        }

        // -------- flush staged outputs every 8 steps --------
        __syncthreads();
        if ((t & 7) == 7) {
            int g = tid >> 7, j = tid & 127;
            float4 v0 = *(float4*)&s_out[(g * Vv + j) * 8 + 0];
            float4 v1 = *(float4*)&s_out[(g * Vv + j) * 8 + 4];
            float4* dst = (float4*)(outp + ((size_t)(b0 + g) * Vv + j) * Tt + (t - 7));
            dst[0] = v0;
            dst[1] = v1;
            __syncthreads();
        }
    }
}

// ---------------- launch ----------------
extern "C" void kernel_launch(void* const* d_in, const int* in_sizes, int n_in,
                              void* d_out, int out_size)
{
    const float* x      = (const float*)d_in[0];
    const int*   y      = (const int*)  d_in[1];
    const float* emb    = (const float*)d_in[2];
    const float* attn_w = (const float*)d_in[3];
    const float* attn_b = (const float*)d_in[4];
    const float* comb_w = (const float*)d_in[5];
    const float* comb_b = (const float*)d_in[6];
    const float* gih    = (const float*)d_in[7];
    const float* ghh    = (const float*)d_in[8];
    const float* gbi    = (const float*)d_in[9];
    const float* gbh    = (const float*)d_in[10];
    const float* out_w  = (const float*)d_in[11];
    const float* out_b  = (const float*)d_in[12];

    float* outp  = (float*)d_out;                        // [B,V,T]
    float* attnp = (float*)d_out + (size_t)Bb * Vv * Tt; // [B,T,L]

    cudaFuncSetAttribute(decoder_kernel,
                         cudaFuncAttributeMaxDynamicSharedMemorySize, SMEM_BYTES);

    pack_all_kernel<<<PACK_BLOCKS + ENC_BLOCKS, 256>>>(attn_w, comb_w, gih, ghh, out_w, x);
    precompute_tok_kernel<<<2 * Vv, Hh>>>(emb, attn_w, attn_b, comb_w, comb_b);
    decoder_kernel<<<Bb / G, NTH, SMEM_BYTES>>>(y, gbi, gbh, out_b, outp, attnp);
}

// round 12
// speedup vs baseline: 1.1507x; 1.1507x over previous
#include <cuda_runtime.h>
#include <cuda_fp16.h>
#include <math.h>

#define Bb   512
#define Hh   256
#define Ld   256
#define Tt   64
#define Vv   128
#define NL   2
#define G    4
#define NTH  512

// ---------------- packed fp16 weight scratch (transposed + k-interleaved) ------------
// P[(k4*N + j)*4 + c] = W[j*K_src + off + k4*4 + c]; element = __half (uint2 per 4 k).
// attn/comb store only their K=256 dynamic halves (h-part / applied-part).
#define OFF_ATTNH 0         // attn h-part: K=256,N=256 -> 65536
#define OFF_COMBA 65536     // comb applied-part:       -> 65536
#define OFF_GIH   131072    // 2 x 256x768 -> 393216
#define OFF_GHH   524288    // 2 x 256x768 -> 393216
#define OFF_OUT   917504    // 256x128 -> 32768
#define PACK_TOTAL 950272

#define PACK_BLOCKS 3712            // ceil(PACK_TOTAL/256)
#define ENC_BLOCKS  32768           // (512*256*256/4)/256
#define TOK_BLOCKS  256             // 2*V token-table blocks

__device__ __align__(16) __half g_pack[PACK_TOTAL];
__device__ __align__(16) __half g_enc[(size_t)Bb * Hh * Ld];   // fp16 encoder memory
__device__ __align__(16) float  g_Tattn[Vv * Ld];              // emb@attn_w_e^T + attn_b
__device__ __align__(16) float  g_Tcomb[Vv * Hh];              // emb@comb_w_e^T + comb_b

// merged prep: weights + encoder fp16 + token tables, one launch
__global__ void pack_all_kernel(const float* __restrict__ aw, const float* __restrict__ cw,
                                const float* __restrict__ gih, const float* __restrict__ ghh,
                                const float* __restrict__ ow, const float* __restrict__ x,
                                const float* __restrict__ emb, const float* __restrict__ ab,
                                const float* __restrict__ cb)
{
    if (blockIdx.x < PACK_BLOCKS) {
        int i = blockIdx.x * blockDim.x + threadIdx.x;
        if (i >= PACK_TOTAL) return;
        float v;
        if (i < 65536) {                        // attn h-part: W[j][256 + k]
            int c = i & 3, j = (i >> 2) & 255, k4 = i >> 10;
            v = aw[j * 512 + 256 + k4 * 4 + c];
        } else if (i < 131072) {                // comb applied-part: W[j][k]
            int r = i - 65536;
            int c = r & 3, j = (r >> 2) & 255, k4 = r >> 10;
            v = cw[j * 512 + k4 * 4 + c];
        } else if (i < 524288) {                // gru ih: per layer K=256, N=768
            int r = i - 131072;
            int layer = r / 196608; int q = r % 196608;
            int c = q & 3; int t2 = q >> 2; int j = t2 % 768; int k4 = t2 / 768;
            v = gih[layer * 196608 + j * 256 + k4 * 4 + c];
        } else if (i < 917504) {                // gru hh
            int r = i - 524288;
            int layer = r / 196608; int q = r % 196608;
            int c = q & 3; int t2 = q >> 2; int j = t2 % 768; int k4 = t2 / 768;
            v = ghh[layer * 196608 + j * 256 + k4 * 4 + c];
        } else {                                // out: K=256, N=128
            int r = i - 917504;
            int c = r & 3, j = (r >> 2) & 127, k4 = r >> 9;
            v = ow[j * 256 + k4 * 4 + c];
        }
        g_pack[i] = __float2half(v);
    } else if (blockIdx.x < PACK_BLOCKS + ENC_BLOCKS) {
        size_t i = (size_t)(blockIdx.x - PACK_BLOCKS) * blockDim.x + threadIdx.x;
        float4 v = ((const float4*)x)[i];
        __half2 h0 = __floats2half2_rn(v.x, v.y);
        __half2 h1 = __floats2half2_rn(v.z, v.w);
        uint2 o;
        o.x = *(unsigned*)&h0;
        o.y = *(unsigned*)&h1;
        ((uint2*)g_enc)[i] = o;
    } else {
        // token tables: 256 blocks = (tok 0..127) x (attn, comb); fp32 exact
        __shared__ float se[Hh];
        int bid = blockIdx.x - PACK_BLOCKS - ENC_BLOCKS;
        int tok = bid & 127;
        bool isComb = bid >= 128;
        int j = threadIdx.x;                 // 256 threads: output column
        se[j] = emb[tok * Hh + j];
        __syncthreads();
        const float* W = isComb ? (cw + j * 512 + 256) : (aw + j * 512);
        float s = 0.f;
        #pragma unroll 8
        for (int k = 0; k < 256; k++) s += W[k] * se[k];
        if (isComb) g_Tcomb[tok * Hh + j] = s + cb[j];
        else        g_Tattn[tok * Ld + j] = s + ab[j];
    }
}

// ---------------- f32x2 packed math helpers (sm_10x FFMA2) ----------------
typedef unsigned long long u64;

__device__ __forceinline__ void fma2(u64& d, u64 a, u64 b) {
    asm("fma.rn.f32x2 %0, %1, %2, %0;" : "+l"(d) : "l"(a), "l"(b));
}
__device__ __forceinline__ float sum2(u64 v) {
    return __uint_as_float((unsigned)v) + __uint_as_float((unsigned)(v >> 32));
}
__device__ __forceinline__ u64 cvt2(unsigned h) {
    float2 f = __half22float2(*(__half2*)&h);
    return ((u64)__float_as_uint(f.y) << 32) | (u64)__float_as_uint(f.x);
}

// ---------------- vectorized block reduction (4 values, 16 warps) ----------------
__device__ __forceinline__ void block_reduce4(float v[G], float* sm, int tid, bool is_max) {
    __syncthreads();
    #pragma unroll
    for (int g = 0; g < G; g++) {
        #pragma unroll
        for (int o = 16; o > 0; o >>= 1) {
            float oth = __shfl_xor_sync(0xffffffffu, v[g], o);
            v[g] = is_max ? fmaxf(v[g], oth) : (v[g] + oth);
        }
    }
    int wid = tid >> 5;
    if ((tid & 31) == 0) {
        #pragma unroll
        for (int g = 0; g < G; g++) sm[wid * G + g] = v[g];
    }
    __syncthreads();
    #pragma unroll
    for (int g = 0; g < G; g++) {
        float r = sm[g];
        #pragma unroll
        for (int w = 1; w < 16; w++)
            r = is_max ? fmaxf(r, sm[w * G + g]) : (r + sm[w * G + g]);
        v[g] = r;
    }
}

// ---------------- main persistent decoder kernel (R10 structure) ----------------
__global__ __launch_bounds__(NTH)
void decoder_kernel(const int*   __restrict__ y,      // [B,T]
                    const float* __restrict__ gbi,    // [2,768]
                    const float* __restrict__ gbh,    // [2,768]
                    const float* __restrict__ out_b,  // [V]
                    float* __restrict__ outp,         // [B,V,T]
                    float* __restrict__ attnp)        // [B,T,L]
{
    __shared__ __align__(16) float s_h  [NL][G][Hh];
    __shared__ __align__(16) float s_aw [G][Ld];
    __shared__ __align__(16) float s_app[G][Hh];
    __shared__ __align__(16) float s_x  [G][Hh];
    __shared__ __align__(16) float s_p2 [G][3][Hh];
    __shared__ __align__(16) float s_out[G][Vv][8];
    __shared__ float s_red[16 * G];
    __shared__ int   s_tok[G];

    const int tid  = threadIdx.x;
    const int wid  = tid >> 5;
    const int lane = tid & 31;
    const int jj   = tid & 255;
    const bool hi  = (tid >= 256);
    const int b0   = blockIdx.x * G;

    const __half* Pattnh = g_pack + OFF_ATTNH;
    const __half* Pcomba = g_pack + OFF_COMBA;
    const __half* Pgih   = g_pack + OFF_GIH;
    const __half* Pghh   = g_pack + OFF_GHH;
    const __half* Pout   = g_pack + OFF_OUT;

    for (int i = tid; i < NL * G * Hh; i += NTH)
        (&s_h[0][0][0])[i] = 0.f;
    __syncthreads();

    for (int t = 0; t < Tt; t++) {
        // -------- token fetch (teacher forcing; SOS=0 at t=0) --------
        if (tid < G)
            s_tok[tid] = (t == 0) ? 0 : y[(b0 + tid) * Tt + t - 1];
        __syncthreads();

        // -------- attention scores: h-part split lo/hi K-halves; e-part from table ----
        {
            u64 acc[G] = {0, 0, 0, 0};
            const uint2* W = (const uint2*)Pattnh + (hi ? 32 * 256 : 0) + jj;
            const int kbase = hi ? 32 : 0;
            #pragma unroll 8
            for (int k4 = 0; k4 < 32; k4++) {
                uint2 wh = W[k4 * 256];
                u64 wx = cvt2(wh.x), wy = cvt2(wh.y);
                #pragma unroll
                for (int g = 0; g < G; g++) {
                    ulonglong2 xv = ((const ulonglong2*)(&s_h[0][g][0]))[kbase + k4];
                    fma2(acc[g], wx, xv.x);
                    fma2(acc[g], wy, xv.y);
                }
            }
            if (hi) {
                #pragma unroll
                for (int g = 0; g < G; g++) s_p2[g][0][jj] = sum2(acc[g]);
            }
            __syncthreads();

            // softmax over L per row (true values in lo half; table adds e-part+bias)
            float sc[G];
            #pragma unroll
            for (int g = 0; g < G; g++)
                sc[g] = hi ? -1e30f
                           : (sum2(acc[g]) + s_p2[g][0][jj] + g_Tattn[s_tok[g] * Ld + jj]);
            float m[G];
            #pragma unroll
            for (int g = 0; g < G; g++) m[g] = sc[g];
            block_reduce4(m, s_red, tid, true);
            float p[G];
            #pragma unroll
            for (int g = 0; g < G; g++) p[g] = hi ? 0.f : __expf(sc[g] - m[g]);
            float s[G];
            #pragma unroll
            for (int g = 0; g < G; g++) s[g] = p[g];
            block_reduce4(s, s_red, tid, false);
            if (!hi) {
                #pragma unroll
                for (int g = 0; g < G; g++) {
                    float a = p[g] * (1.f / s[g]);
                    s_aw[g][jj] = a;
                    attnp[((size_t)(b0 + g) * Tt + t) * Ld + jj] = a;
                }
            }
            __syncthreads();
        }

        // -------- applied = aw @ enc (fp16 enc, warp owns fixed row g) --------
        {
            const int g = wid >> 2;                    // 4 warps per batch row
            const int hbase = (wid & 3) * 64;          // 64 h-values per warp
            const float4* awp = (const float4*)(s_aw[g]);
            const float4 A0 = awp[lane * 2];
            const float4 A1 = awp[lane * 2 + 1];
            const uint4* xrow =
                (const uint4*)(g_enc + ((size_t)(b0 + g) * Hh + hbase) * Ld) + lane;
            #pragma unroll
            for (int it = 0; it < 64; it += 8) {
                uint4 xv[8];
                #pragma unroll
                for (int u = 0; u < 8; u++) xv[u] = xrow[(it + u) * 32];
                float d[8];
                #pragma unroll
                for (int u = 0; u < 8; u++) {
                    float2 f0 = __half22float2(*(__half2*)&xv[u].x);
                    float2 f1 = __half22float2(*(__half2*)&xv[u].y);
                    float2 f2 = __half22float2(*(__half2*)&xv[u].z);
                    float2 f3 = __half22float2(*(__half2*)&xv[u].w);
                    d[u] = f0.x * A0.x + f0.y * A0.y + f1.x * A0.z + f1.y * A0.w
                         + f2.x * A1.x + f2.y * A1.y + f3.x * A1.z + f3.y * A1.w;
                }
                #pragma unroll
                for (int u = 0; u < 8; u++) {
                    #pragma unroll
                    for (int o = 16; o > 0; o >>= 1)
                        d[u] += __shfl_xor_sync(0xffffffffu, d[u], o);
                }
                if (lane == 0) {
                    #pragma unroll
                    for (int u = 0; u < 8; u++) s_app[g][hbase + it + u] = d[u];
                }
            }
        }
        __syncthreads();

        // -------- combine: applied-part split lo/hi K-halves; e-part from table -------
        {
            u64 acc[G] = {0, 0, 0, 0};
            const uint2* W = (const uint2*)Pcomba + (hi ? 32 * 256 : 0) + jj;
            const int kbase = hi ? 32 : 0;
            #pragma unroll 8
            for (int k4 = 0; k4 < 32; k4++) {
                uint2 wh = W[k4 * 256];
                u64 wx = cvt2(wh.x), wy = cvt2(wh.y);
                #pragma unroll
                for (int g = 0; g < G; g++) {
                    ulonglong2 xv = ((const ulonglong2*)(&s_app[g][0]))[kbase + k4];
                    fma2(acc[g], wx, xv.x);
                    fma2(acc[g], wy, xv.y);
                }
            }
            if (hi) {
                #pragma unroll
                for (int g = 0; g < G; g++) s_p2[g][0][jj] = sum2(acc[g]);
            }
            __syncthreads();
            if (!hi) {
                #pragma unroll
                for (int g = 0; g < G; g++)
                    s_x[g][jj] = fmaxf(sum2(acc[g]) + s_p2[g][0][jj]
                                       + g_Tcomb[s_tok[g] * Hh + jj], 0.f);
            }
            __syncthreads();
        }

        // -------- GRU layers: lo half = ih matvec, hi half = hh matvec --------
        #pragma unroll
        for (int l = 0; l < NL; l++) {
            u64 a0[G] = {0,0,0,0}, a1[G] = {0,0,0,0}, a2[G] = {0,0,0,0};
            const uint2* W =
                (const uint2*)((hi ? Pghh : Pgih) + l * 196608) + jj;
            const float* vb = hi ? &s_h[l][0][0] : &s_x[0][0];
            #pragma unroll 4
            for (int k4 = 0; k4 < 64; k4++) {
                uint2 wh0 = W[k4 * 768];
                uint2 wh1 = W[k4 * 768 + 256];
                uint2 wh2 = W[k4 * 768 + 512];
                u64 w0x = cvt2(wh0.x), w0y = cvt2(wh0.y);
                u64 w1x = cvt2(wh1.x), w1y = cvt2(wh1.y);
                u64 w2x = cvt2(wh2.x), w2y = cvt2(wh2.y);
                #pragma unroll
                for (int g = 0; g < G; g++) {
                    ulonglong2 xv = ((const ulonglong2*)(vb + g * Hh))[k4];
                    fma2(a0[g], w0x, xv.x); fma2(a0[g], w0y, xv.y);
                    fma2(a1[g], w1x, xv.x); fma2(a1[g], w1y, xv.y);
                    fma2(a2[g], w2x, xv.x); fma2(a2[g], w2y, xv.y);
                }
            }
            if (hi) {
                #pragma unroll
                for (int g = 0; g < G; g++) {
                    s_p2[g][0][jj] = sum2(a0[g]);
                    s_p2[g][1][jj] = sum2(a1[g]);
                    s_p2[g][2][jj] = sum2(a2[g]);
                }
            }
            __syncthreads();
            if (!hi) {
                const float bi0 = gbi[l * 768 + jj];
                const float bi1 = gbi[l * 768 + 256 + jj];
                const float bi2 = gbi[l * 768 + 512 + jj];
                const float bh0 = gbh[l * 768 + jj];
                const float bh1 = gbh[l * 768 + 256 + jj];
                const float bh2 = gbh[l * 768 + 512 + jj];
                #pragma unroll
                for (int g = 0; g < G; g++) {
                    float hprev = s_h[l][g][jj];
                    float i0 = sum2(a0[g]) + bi0, h0 = s_p2[g][0][jj] + bh0;
                    float i1 = sum2(a1[g]) + bi1, h1 = s_p2[g][1][jj] + bh1;
                    float i2 = sum2(a2[g]) + bi2, h2 = s_p2[g][2][jj] + bh2;
                    float r = 1.f / (1.f + __expf(-(i0 + h0)));
                    float z = 1.f / (1.f + __expf(-(i1 + h1)));
                    float n = tanhf(i2 + r * h2);
                    float hn = (1.f - z) * n + z * hprev;
                    s_h[l][g][jj] = hn;
                    s_x[g][jj]    = hn;
                }
            }
            __syncthreads();
        }

        // -------- output projection (K split 4 ways) + log_softmax --------
        {
            int j  = tid & 127;
            int sl = tid >> 7;
            u64 acc[G] = {0, 0, 0, 0};
            const uint2* W = (const uint2*)Pout + j;
            #pragma unroll 8
            for (int k4 = sl * 16; k4 < sl * 16 + 16; k4++) {
                uint2 wh = W[k4 * 128];
                u64 wx = cvt2(wh.x), wy = cvt2(wh.y);
                #pragma unroll
                for (int g = 0; g < G; g++) {
                    ulonglong2 hv = ((const ulonglong2*)s_x[g])[k4];
                    fma2(acc[g], wx, hv.x);
                    fma2(acc[g], wy, hv.y);
                }
            }
            float* s_op = &s_p2[0][0][0];
            #pragma unroll
            for (int g = 0; g < G; g++) s_op[(g * 4 + sl) * 128 + j] = sum2(acc[g]);
            __syncthreads();

            float oacc[G];
            #pragma unroll
            for (int g = 0; g < G; g++) {
                oacc[g] = (tid < 128)
                    ? (out_b[j] + s_op[(g * 4 + 0) * 128 + j] + s_op[(g * 4 + 1) * 128 + j]
                               + s_op[(g * 4 + 2) * 128 + j] + s_op[(g * 4 + 3) * 128 + j])
                    : -1e30f;
            }
            float m[G];
            #pragma unroll
            for (int g = 0; g < G; g++) m[g] = oacc[g];
            block_reduce4(m, s_red, tid, true);
            float p[G];
            #pragma unroll
            for (int g = 0; g < G; g++) p[g] = (tid < 128) ? __expf(oacc[g] - m[g]) : 0.f;
            float s[G];
            #pragma unroll
            for (int g = 0; g < G; g++) s[g] = p[g];
            block_reduce4(s, s_red, tid, false);
            if (tid < 128) {
                #pragma unroll
                for (int g = 0; g < G; g++)
                    s_out[g][j][t & 7] = oacc[g] - m[g] - logf(s[g]);
            }
        }

        // -------- flush staged outputs every 8 steps (coalesced float4 x2) --------
        __syncthreads();
        if ((t & 7) == 7) {
            int g = tid >> 7, j = tid & 127;
            float4 v0 = *(float4*)&s_out[g][j][0];
            float4 v1 = *(float4*)&s_out[g][j][4];
            float4* dst = (float4*)(outp + ((size_t)(b0 + g) * Vv + j) * Tt + (t - 7));
            dst[0] = v0;
            dst[1] = v1;
            __syncthreads();
        }
    }
}

// ---------------- launch ----------------
extern "C" void kernel_launch(void* const* d_in, const int* in_sizes, int n_in,
                              void* d_out, int out_size)
{
    const float* x      = (const float*)d_in[0];
    const int*   y      = (const int*)  d_in[1];
    const float* emb    = (const float*)d_in[2];
    const float* attn_w = (const float*)d_in[3];
    const float* attn_b = (const float*)d_in[4];
    const float* comb_w = (const float*)d_in[5];
    const float* comb_b = (const float*)d_in[6];
    const float* gih    = (const float*)d_in[7];
    const float* ghh    = (const float*)d_in[8];
    const float* gbi    = (const float*)d_in[9];
    const float* gbh    = (const float*)d_in[10];
    const float* out_w  = (const float*)d_in[11];
    const float* out_b  = (const float*)d_in[12];

    float* outp  = (float*)d_out;                        // [B,V,T]
    float* attnp = (float*)d_out + (size_t)Bb * Vv * Tt; // [B,T,L]

    pack_all_kernel<<<PACK_BLOCKS + ENC_BLOCKS + TOK_BLOCKS, 256>>>(
        attn_w, comb_w, gih, ghh, out_w, x, emb, attn_b, comb_b);
    decoder_kernel<<<Bb / G, NTH>>>(y, gbi, gbh, out_b, outp, attnp);
}

// round 13
// speedup vs baseline: 1.1562x; 1.0048x over previous
#include <cuda_runtime.h>
#include <cuda_fp16.h>
#include <cuda_bf16.h>
#include <math.h>

#define Bb   512
#define Hh   256
#define Ld   256
#define Tt   64
#define Vv   128
#define NL   2
#define G    4
#define NTH  512

// ---------------- packed bf16 weight scratch (transposed + k-interleaved) ------------
// P[(k4*N + j)*4 + c] = W[j*K_src + off + k4*4 + c]; element = bf16 (uint2 per 4 k).
#define OFF_ATTNH 0         // attn h-part: K=256,N=256 -> 65536
#define OFF_COMBA 65536     // comb applied-part:       -> 65536
#define OFF_GIH   131072    // 2 x 256x768 -> 393216
#define OFF_GHH   524288    // 2 x 256x768 -> 393216
#define OFF_OUT   917504    // 256x128 -> 32768
#define PACK_TOTAL 950272

#define PACK_BLOCKS 3712            // ceil(PACK_TOTAL/256)
#define ENC_BLOCKS  32768           // (512*256*256/4)/256
#define TOK_BLOCKS  256             // 2*V token-table blocks

__device__ __align__(16) __nv_bfloat16 g_pack[PACK_TOTAL];
__device__ __align__(16) __half g_enc[(size_t)Bb * Hh * Ld];   // fp16 encoder memory
__device__ __align__(16) float  g_Tattn[Vv * Ld];              // emb@attn_w_e^T + attn_b
__device__ __align__(16) float  g_Tcomb[Vv * Hh];              // emb@comb_w_e^T + comb_b

// merged prep: weights + encoder fp16 + token tables, one launch
__global__ void pack_all_kernel(const float* __restrict__ aw, const float* __restrict__ cw,
                                const float* __restrict__ gih, const float* __restrict__ ghh,
                                const float* __restrict__ ow, const float* __restrict__ x,
                                const float* __restrict__ emb, const float* __restrict__ ab,
                                const float* __restrict__ cb)
{
    if (blockIdx.x < PACK_BLOCKS) {
        int i = blockIdx.x * blockDim.x + threadIdx.x;
        if (i >= PACK_TOTAL) return;
        float v;
        if (i < 65536) {                        // attn h-part: W[j][256 + k]
            int c = i & 3, j = (i >> 2) & 255, k4 = i >> 10;
            v = aw[j * 512 + 256 + k4 * 4 + c];
        } else if (i < 131072) {                // comb applied-part: W[j][k]
            int r = i - 65536;
            int c = r & 3, j = (r >> 2) & 255, k4 = r >> 10;
            v = cw[j * 512 + k4 * 4 + c];
        } else if (i < 524288) {                // gru ih: per layer K=256, N=768
            int r = i - 131072;
            int layer = r / 196608; int q = r % 196608;
            int c = q & 3; int t2 = q >> 2; int j = t2 % 768; int k4 = t2 / 768;
            v = gih[layer * 196608 + j * 256 + k4 * 4 + c];
        } else if (i < 917504) {                // gru hh
            int r = i - 524288;
            int layer = r / 196608; int q = r % 196608;
            int c = q & 3; int t2 = q >> 2; int j = t2 % 768; int k4 = t2 / 768;
            v = ghh[layer * 196608 + j * 256 + k4 * 4 + c];
        } else {                                // out: K=256, N=128
            int r = i - 917504;
            int c = r & 3, j = (r >> 2) & 127, k4 = r >> 9;
            v = ow[j * 256 + k4 * 4 + c];
        }
        g_pack[i] = __float2bfloat16(v);
    } else if (blockIdx.x < PACK_BLOCKS + ENC_BLOCKS) {
        size_t i = (size_t)(blockIdx.x - PACK_BLOCKS) * blockDim.x + threadIdx.x;
        float4 v = ((const float4*)x)[i];
        __half2 h0 = __floats2half2_rn(v.x, v.y);
        __half2 h1 = __floats2half2_rn(v.z, v.w);
        uint2 o;
        o.x = *(unsigned*)&h0;
        o.y = *(unsigned*)&h1;
        ((uint2*)g_enc)[i] = o;
    } else {
        // token tables: 256 blocks = (tok 0..127) x (attn, comb); fp32 exact
        __shared__ float se[Hh];
        int bid = blockIdx.x - PACK_BLOCKS - ENC_BLOCKS;
        int tok = bid & 127;
        bool isComb = bid >= 128;
        int j = threadIdx.x;                 // 256 threads: output column
        se[j] = emb[tok * Hh + j];
        __syncthreads();
        const float* W = isComb ? (cw + j * 512 + 256) : (aw + j * 512);
        float s = 0.f;
        #pragma unroll 8
        for (int k = 0; k < 256; k++) s += W[k] * se[k];
        if (isComb) g_Tcomb[tok * Hh + j] = s + cb[j];
        else        g_Tattn[tok * Ld + j] = s + ab[j];
    }
}

// ---------------- f32x2 packed math helpers (sm_10x FFMA2) ----------------
typedef unsigned long long u64;

__device__ __forceinline__ void fma2(u64& d, u64 a, u64 b) {
    asm("fma.rn.f32x2 %0, %1, %2, %0;" : "+l"(d) : "l"(a), "l"(b));
}
__device__ __forceinline__ float sum2(u64 v) {
    return __uint_as_float((unsigned)v) + __uint_as_float((unsigned)(v >> 32));
}
// bf16x2 -> packed f32x2: pure ALU bit ops (SHF + LOP), exact.
// u32 = (bf(w1)<<16) | bf(w0); f32(w0) = u<<16, f32(w1) = u & 0xFFFF0000.
__device__ __forceinline__ u64 cvt2(unsigned u) {
    return ((u64)(u & 0xFFFF0000u) << 32) | (u64)(u << 16);
}

// ---------------- vectorized block reduction (4 values, 16 warps) ----------------
__device__ __forceinline__ void block_reduce4(float v[G], float* sm, int tid, bool is_max) {
    __syncthreads();
    #pragma unroll
    for (int g = 0; g < G; g++) {
        #pragma unroll
        for (int o = 16; o > 0; o >>= 1) {
            float oth = __shfl_xor_sync(0xffffffffu, v[g], o);
            v[g] = is_max ? fmaxf(v[g], oth) : (v[g] + oth);
        }
    }
    int wid = tid >> 5;
    if ((tid & 31) == 0) {
        #pragma unroll
        for (int g = 0; g < G; g++) sm[wid * G + g] = v[g];
    }
    __syncthreads();
    #pragma unroll
    for (int g = 0; g < G; g++) {
        float r = sm[g];
        #pragma unroll
        for (int w = 1; w < 16; w++)
            r = is_max ? fmaxf(r, sm[w * G + g]) : (r + sm[w * G + g]);
        v[g] = r;
    }
}

// ---------------- main persistent decoder kernel (R10/R12 structure) ----------------
__global__ __launch_bounds__(NTH)
void decoder_kernel(const int*   __restrict__ y,      // [B,T]
                    const float* __restrict__ gbi,    // [2,768]
                    const float* __restrict__ gbh,    // [2,768]
                    const float* __restrict__ out_b,  // [V]
                    float* __restrict__ outp,         // [B,V,T]
                    float* __restrict__ attnp)        // [B,T,L]
{
    __shared__ __align__(16) float s_h  [NL][G][Hh];
    __shared__ __align__(16) float s_aw [G][Ld];
    __shared__ __align__(16) float s_app[G][Hh];
    __shared__ __align__(16) float s_x  [G][Hh];
    __shared__ __align__(16) float s_p2 [G][3][Hh];
    __shared__ __align__(16) float s_out[G][Vv][8];
    __shared__ float s_red[16 * G];
    __shared__ int   s_tok[G];

    const int tid  = threadIdx.x;
    const int wid  = tid >> 5;
    const int lane = tid & 31;
    const int jj   = tid & 255;
    const bool hi  = (tid >= 256);
    const int b0   = blockIdx.x * G;

    const __nv_bfloat16* Pattnh = g_pack + OFF_ATTNH;
    const __nv_bfloat16* Pcomba = g_pack + OFF_COMBA;
    const __nv_bfloat16* Pgih   = g_pack + OFF_GIH;
    const __nv_bfloat16* Pghh   = g_pack + OFF_GHH;
    const __nv_bfloat16* Pout   = g_pack + OFF_OUT;

    for (int i = tid; i < NL * G * Hh; i += NTH)
        (&s_h[0][0][0])[i] = 0.f;
    __syncthreads();

    for (int t = 0; t < Tt; t++) {
        // -------- token fetch (teacher forcing; SOS=0 at t=0) --------
        if (tid < G)
            s_tok[tid] = (t == 0) ? 0 : y[(b0 + tid) * Tt + t - 1];
        __syncthreads();

        // -------- attention scores: h-part split lo/hi K-halves; e-part from table ----
        {
            u64 acc[G] = {0, 0, 0, 0};
            const uint2* W = (const uint2*)Pattnh + (hi ? 32 * 256 : 0) + jj;
            const int kbase = hi ? 32 : 0;
            #pragma unroll 8
            for (int k4 = 0; k4 < 32; k4++) {
                uint2 wh = W[k4 * 256];
                u64 wx = cvt2(wh.x), wy = cvt2(wh.y);
                #pragma unroll
                for (int g = 0; g < G; g++) {
                    ulonglong2 xv = ((const ulonglong2*)(&s_h[0][g][0]))[kbase + k4];
                    fma2(acc[g], wx, xv.x);
                    fma2(acc[g], wy, xv.y);
                }
            }
            if (hi) {
                #pragma unroll
                for (int g = 0; g < G; g++) s_p2[g][0][jj] = sum2(acc[g]);
            }
            __syncthreads();

            // softmax over L per row (true values in lo half; table adds e-part+bias)
            float sc[G];
            #pragma unroll
            for (int g = 0; g < G; g++)
                sc[g] = hi ? -1e30f
                           : (sum2(acc[g]) + s_p2[g][0][jj] + g_Tattn[s_tok[g] * Ld + jj]);
            float m[G];
            #pragma unroll
            for (int g = 0; g < G; g++) m[g] = sc[g];
            block_reduce4(m, s_red, tid, true);
            float p[G];
            #pragma unroll
            for (int g = 0; g < G; g++) p[g] = hi ? 0.f : __expf(sc[g] - m[g]);
            float s[G];
            #pragma unroll
            for (int g = 0; g < G; g++) s[g] = p[g];
            block_reduce4(s, s_red, tid, false);
            if (!hi) {
                #pragma unroll
                for (int g = 0; g < G; g++) {
                    float a = p[g] * (1.f / s[g]);
                    s_aw[g][jj] = a;
                    attnp[((size_t)(b0 + g) * Tt + t) * Ld + jj] = a;
                }
            }
            __syncthreads();
        }

        // -------- applied = aw @ enc (fp16 enc, warp owns fixed row g) --------
        {
            const int g = wid >> 2;                    // 4 warps per batch row
            const int hbase = (wid & 3) * 64;          // 64 h-values per warp
            const float4* awp = (const float4*)(s_aw[g]);
            const float4 A0 = awp[lane * 2];
            const float4 A1 = awp[lane * 2 + 1];
            const uint4* xrow =
                (const uint4*)(g_enc + ((size_t)(b0 + g) * Hh + hbase) * Ld) + lane;
            #pragma unroll
            for (int it = 0; it < 64; it += 8) {
                uint4 xv[8];
                #pragma unroll
                for (int u = 0; u < 8; u++) xv[u] = xrow[(it + u) * 32];
                float d[8];
                #pragma unroll
                for (int u = 0; u < 8; u++) {
                    float2 f0 = __half22float2(*(__half2*)&xv[u].x);
                    float2 f1 = __half22float2(*(__half2*)&xv[u].y);
                    float2 f2 = __half22float2(*(__half2*)&xv[u].z);
                    float2 f3 = __half22float2(*(__half2*)&xv[u].w);
                    d[u] = f0.x * A0.x + f0.y * A0.y + f1.x * A0.z + f1.y * A0.w
                         + f2.x * A1.x + f2.y * A1.y + f3.x * A1.z + f3.y * A1.w;
                }
                #pragma unroll
                for (int u = 0; u < 8; u++) {
                    #pragma unroll
                    for (int o = 16; o > 0; o >>= 1)
                        d[u] += __shfl_xor_sync(0xffffffffu, d[u], o);
                }
                if (lane == 0) {
                    #pragma unroll
                    for (int u = 0; u < 8; u++) s_app[g][hbase + it + u] = d[u];
                }
            }
        }
        __syncthreads();

        // -------- combine: applied-part split lo/hi K-halves; e-part from table -------
        {
            u64 acc[G] = {0, 0, 0, 0};
            const uint2* W = (const uint2*)Pcomba + (hi ? 32 * 256 : 0) + jj;
            const int kbase = hi ? 32 : 0;
            #pragma unroll 8
            for (int k4 = 0; k4 < 32; k4++) {
                uint2 wh = W[k4 * 256];
                u64 wx = cvt2(wh.x), wy = cvt2(wh.y);
                #pragma unroll
                for (int g = 0; g < G; g++) {
                    ulonglong2 xv = ((const ulonglong2*)(&s_app[g][0]))[kbase + k4];
                    fma2(acc[g], wx, xv.x);
                    fma2(acc[g], wy, xv.y);
                }
            }
            if (hi) {
                #pragma unroll
                for (int g = 0; g < G; g++) s_p2[g][0][jj] = sum2(acc[g]);
            }
            __syncthreads();
            if (!hi) {
                #pragma unroll
                for (int g = 0; g < G; g++)
                    s_x[g][jj] = fmaxf(sum2(acc[g]) + s_p2[g][0][jj]
                                       + g_Tcomb[s_tok[g] * Hh + jj], 0.f);
            }
            __syncthreads();
        }

        // -------- GRU layers: lo half = ih matvec, hi half = hh matvec --------
        #pragma unroll
        for (int l = 0; l < NL; l++) {
            u64 a0[G] = {0,0,0,0}, a1[G] = {0,0,0,0}, a2[G] = {0,0,0,0};
            const uint2* W =
                (const uint2*)((hi ? Pghh : Pgih) + l * 196608) + jj;
            const float* vb = hi ? &s_h[l][0][0] : &s_x[0][0];
            #pragma unroll 4
            for (int k4 = 0; k4 < 64; k4++) {
                uint2 wh0 = W[k4 * 768];
                uint2 wh1 = W[k4 * 768 + 256];
                uint2 wh2 = W[k4 * 768 + 512];
                u64 w0x = cvt2(wh0.x), w0y = cvt2(wh0.y);
                u64 w1x = cvt2(wh1.x), w1y = cvt2(wh1.y);
                u64 w2x = cvt2(wh2.x), w2y = cvt2(wh2.y);
                #pragma unroll
                for (int g = 0; g < G; g++) {
                    ulonglong2 xv = ((const ulonglong2*)(vb + g * Hh))[k4];
                    fma2(a0[g], w0x, xv.x); fma2(a0[g], w0y, xv.y);
                    fma2(a1[g], w1x, xv.x); fma2(a1[g], w1y, xv.y);
                    fma2(a2[g], w2x, xv.x); fma2(a2[g], w2y, xv.y);
                }
            }
            if (hi) {
                #pragma unroll
                for (int g = 0; g < G; g++) {
                    s_p2[g][0][jj] = sum2(a0[g]);
                    s_p2[g][1][jj] = sum2(a1[g]);
                    s_p2[g][2][jj] = sum2(a2[g]);
                }
            }
            __syncthreads();
            if (!hi) {
                const float bi0 = gbi[l * 768 + jj];
                const float bi1 = gbi[l * 768 + 256 + jj];
                const float bi2 = gbi[l * 768 + 512 + jj];
                const float bh0 = gbh[l * 768 + jj];
                const float bh1 = gbh[l * 768 + 256 + jj];
                const float bh2 = gbh[l * 768 + 512 + jj];
                #pragma unroll
                for (int g = 0; g < G; g++) {
                    float hprev = s_h[l][g][jj];
                    float i0 = sum2(a0[g]) + bi0, h0 = s_p2[g][0][jj] + bh0;
                    float i1 = sum2(a1[g]) + bi1, h1 = s_p2[g][1][jj] + bh1;
                    float i2 = sum2(a2[g]) + bi2, h2 = s_p2[g][2][jj] + bh2;
                    float r = 1.f / (1.f + __expf(-(i0 + h0)));
                    float z = 1.f / (1.f + __expf(-(i1 + h1)));
                    float n = tanhf(i2 + r * h2);
                    float hn = (1.f - z) * n + z * hprev;
                    s_h[l][g][jj] = hn;
                    s_x[g][jj]    = hn;
                }
            }
            __syncthreads();
        }

        // -------- output projection (K split 4 ways) + log_softmax --------
        {
            int j  = tid & 127;
            int sl = tid >> 7;
            u64 acc[G] = {0, 0, 0, 0};
            const uint2* W = (const uint2*)Pout + j;
            #pragma unroll 8
            for (int k4 = sl * 16; k4 < sl * 16 + 16; k4++) {
                uint2 wh = W[k4 * 128];
                u64 wx = cvt2(wh.x), wy = cvt2(wh.y);
                #pragma unroll
                for (int g = 0; g < G; g++) {
                    ulonglong2 hv = ((const ulonglong2*)s_x[g])[k4];
                    fma2(acc[g], wx, hv.x);
                    fma2(acc[g], wy, hv.y);
                }
            }
            float* s_op = &s_p2[0][0][0];
            #pragma unroll
            for (int g = 0; g < G; g++) s_op[(g * 4 + sl) * 128 + j] = sum2(acc[g]);
            __syncthreads();

            float oacc[G];
            #pragma unroll
            for (int g = 0; g < G; g++) {
                oacc[g] = (tid < 128)
                    ? (out_b[j] + s_op[(g * 4 + 0) * 128 + j] + s_op[(g * 4 + 1) * 128 + j]
                               + s_op[(g * 4 + 2) * 128 + j] + s_op[(g * 4 + 3) * 128 + j])
                    : -1e30f;
            }
            float m[G];
            #pragma unroll
            for (int g = 0; g < G; g++) m[g] = oacc[g];
            block_reduce4(m, s_red, tid, true);
            float p[G];
            #pragma unroll
            for (int g = 0; g < G; g++) p[g] = (tid < 128) ? __expf(oacc[g] - m[g]) : 0.f;
            float s[G];
            #pragma unroll
            for (int g = 0; g < G; g++) s[g] = p[g];
            block_reduce4(s, s_red, tid, false);
            if (tid < 128) {
                #pragma unroll
                for (int g = 0; g < G; g++)
                    s_out[g][j][t & 7] = oacc[g] - m[g] - logf(s[g]);
            }
        }

        // -------- flush staged outputs every 8 steps (coalesced float4 x2) --------
        __syncthreads();
        if ((t & 7) == 7) {
            int g = tid >> 7, j = tid & 127;
            float4 v0 = *(float4*)&s_out[g][j][0];
            float4 v1 = *(float4*)&s_out[g][j][4];
            float4* dst = (float4*)(outp + ((size_t)(b0 + g) * Vv + j) * Tt + (t - 7));
            dst[0] = v0;
            dst[1] = v1;
            __syncthreads();
        }
    }
}

// ---------------- launch ----------------
extern "C" void kernel_launch(void* const* d_in, const int* in_sizes, int n_in,
                              void* d_out, int out_size)
{
    const float* x      = (const float*)d_in[0];
    const int*   y      = (const int*)  d_in[1];
    const float* emb    = (const float*)d_in[2];
    const float* attn_w = (const float*)d_in[3];
    const float* attn_b = (const float*)d_in[4];
    const float* comb_w = (const float*)d_in[5];
    const float* comb_b = (const float*)d_in[6];
    const float* gih    = (const float*)d_in[7];
    const float* ghh    = (const float*)d_in[8];
    const float* gbi    = (const float*)d_in[9];
    const float* gbh    = (const float*)d_in[10];
    const float* out_w  = (const float*)d_in[11];
    const float* out_b  = (const float*)d_in[12];

    float* outp  = (float*)d_out;                        // [B,V,T]
    float* attnp = (float*)d_out + (size_t)Bb * Vv * Tt; // [B,T,L]

    pack_all_kernel<<<PACK_BLOCKS + ENC_BLOCKS + TOK_BLOCKS, 256>>>(
        attn_w, comb_w, gih, ghh, out_w, x, emb, attn_b, comb_b);
    decoder_kernel<<<Bb / G, NTH>>>(y, gbi, gbh, out_b, outp, attnp);
}

// round 14
// speedup vs baseline: 1.1641x; 1.0068x over previous
#include <cuda_runtime.h>
#include <cuda_fp16.h>
#include <cuda_bf16.h>
#include <math.h>

#define Bb   512
#define Hh   256
#define Ld   256
#define Tt   64
#define Vv   128
#define NL   2
#define G    4
#define NTH  512

// ---------------- packed bf16 weights ----------------
// attn-h/comb-a: P[(k4*256 + j)*4 + c] = W[j][off + k4*4 + c]  (uint2 per 4 k)
// GRU: 32B groups: group(k4,jj) holds 16 bf16 = [w0 k4*4..+3 for n=jj][w1 for n=jj+256]
//      [w2 for n=jj+512][pad]; one uint4 + uint2 load per (k4,jj).
// out: P[(k4*128 + j)*4 + c] = W[j][k4*4 + c]
#define OFF_ATTNH 0          // 65536
#define OFF_COMBA 65536      // 65536
#define OFF_GIH   131072     // 2 x 262144 (padded groups)
#define OFF_GHH   655360     // 2 x 262144
#define OFF_OUT   1179648    // 32768
#define PACK_TOTAL 1212416

#define PACK_BLOCKS 4736     // ceil(PACK_TOTAL/256)
#define ENC_BLOCKS  8192     // 512 b x 16 tiles (64h x 64l)
#define TOK_BLOCKS  256

__device__ __align__(16) __nv_bfloat16 g_pack[PACK_TOTAL];
__device__ __align__(16) __nv_bfloat16 g_encT[(size_t)Bb * Ld * Hh];  // [B][L][H] bf16
__device__ __align__(16) float  g_Tattn[Vv * Ld];
__device__ __align__(16) float  g_Tcomb[Vv * Hh];

// merged prep: weights + transposed encoder + token tables
__global__ void pack_all_kernel(const float* __restrict__ aw, const float* __restrict__ cw,
                                const float* __restrict__ gih, const float* __restrict__ ghh,
                                const float* __restrict__ ow, const float* __restrict__ x,
                                const float* __restrict__ emb, const float* __restrict__ ab,
                                const float* __restrict__ cb)
{
    if (blockIdx.x < PACK_BLOCKS) {
        int i = blockIdx.x * blockDim.x + threadIdx.x;
        if (i >= PACK_TOTAL) return;
        float v;
        if (i < 65536) {                        // attn h-part: W[j][256 + k]
            int c = i & 3, j = (i >> 2) & 255, k4 = i >> 10;
            v = aw[j * 512 + 256 + k4 * 4 + c];
        } else if (i < 131072) {                // comb applied-part: W[j][k]
            int r = i - 65536;
            int c = r & 3, j = (r >> 2) & 255, k4 = r >> 10;
            v = cw[j * 512 + k4 * 4 + c];
        } else if (i < 1179648) {               // gru grouped (ih then hh)
            int r = i - 131072;
            const float* W = (r < 524288) ? gih : ghh;
            int r2 = r & 524287;
            int layer = r2 >> 18;               // /262144
            int q = r2 & 262143;
            int w  = q & 15;                    // within 32B group
            int grp = q >> 4;                   // k4*256 + jj
            int jj = grp & 255, k4 = grp >> 8;
            int sl = w >> 2, c = w & 3;
            v = (sl < 3) ? W[layer * 196608 + (jj + sl * 256) * 256 + k4 * 4 + c] : 0.f;
        } else {                                // out
            int r = i - 1179648;
            int c = r & 3, j = (r >> 2) & 127, k4 = r >> 9;
            v = ow[j * 256 + k4 * 4 + c];
        }
        g_pack[i] = __float2bfloat16(v);
    } else if (blockIdx.x < PACK_BLOCKS + ENC_BLOCKS) {
        // encoder transpose: x[B][H][1][L] -> g_encT[B][L][H], 64x64 tiles via SMEM
        __shared__ float tile[64][65];
        int bid = blockIdx.x - PACK_BLOCKS;
        int b  = bid >> 4;
        int tl = bid & 15;
        int h0 = (tl >> 2) * 64;
        int l0 = (tl & 3) * 64;
        int t = threadIdx.x;
        #pragma unroll
        for (int i = 0; i < 16; i++) {
            int idx = i * 256 + t;
            int r = idx >> 6, c = idx & 63;     // r = h-local, c = l-local
            tile[r][c] = x[((size_t)b * Hh + h0 + r) * Ld + l0 + c];
        }
        __syncthreads();
        #pragma unroll
        for (int i = 0; i < 16; i++) {
            int idx = i * 256 + t;
            int r = idx >> 6, c = idx & 63;     // r = l-local, c = h-local
            g_encT[((size_t)b * Ld + l0 + r) * Hh + h0 + c] = __float2bfloat16(tile[c][r]);
        }
    } else {
        __shared__ float se[Hh];
        int bid = blockIdx.x - PACK_BLOCKS - ENC_BLOCKS;
        int tok = bid & 127;
        bool isComb = bid >= 128;
        int j = threadIdx.x;
        se[j] = emb[tok * Hh + j];
        __syncthreads();
        const float* W = isComb ? (cw + j * 512 + 256) : (aw + j * 512);
        float s = 0.f;
        #pragma unroll 8
        for (int k = 0; k < 256; k++) s += W[k] * se[k];
        if (isComb) g_Tcomb[tok * Hh + j] = s + cb[j];
        else        g_Tattn[tok * Ld + j] = s + ab[j];
    }
}

// ---------------- f32x2 / bf16 helpers ----------------
typedef unsigned long long u64;

__device__ __forceinline__ void fma2(u64& d, u64 a, u64 b) {
    asm("fma.rn.f32x2 %0, %1, %2, %0;" : "+l"(d) : "l"(a), "l"(b));
}
__device__ __forceinline__ float sum2(u64 v) {
    return __uint_as_float((unsigned)v) + __uint_as_float((unsigned)(v >> 32));
}
// bf16x2 -> packed f32x2 (ALU-only, exact)
__device__ __forceinline__ u64 cvt2(unsigned u) {
    return ((u64)(u & 0xFFFF0000u) << 32) | (u64)(u << 16);
}
// duplicate fp32 scalar into both f32x2 lanes
__device__ __forceinline__ u64 dup2(float a) {
    unsigned ua = __float_as_uint(a);
    return ((u64)ua << 32) | (u64)ua;
}

// ---------------- block reduce (4 values, 16 warps) ----------------
__device__ __forceinline__ void block_reduce4(float v[G], float* sm, int tid, bool is_max) {
    __syncthreads();
    #pragma unroll
    for (int g = 0; g < G; g++) {
        #pragma unroll
        for (int o = 16; o > 0; o >>= 1) {
            float oth = __shfl_xor_sync(0xffffffffu, v[g], o);
            v[g] = is_max ? fmaxf(v[g], oth) : (v[g] + oth);
        }
    }
    int wid = tid >> 5;
    if ((tid & 31) == 0) {
        #pragma unroll
        for (int g = 0; g < G; g++) sm[wid * G + g] = v[g];
    }
    __syncthreads();
    #pragma unroll
    for (int g = 0; g < G; g++) {
        float r = sm[g];
        #pragma unroll
        for (int w = 1; w < 16; w++)
            r = is_max ? fmaxf(r, sm[w * G + g]) : (r + sm[w * G + g]);
        v[g] = r;
    }
}

// ---------------- main persistent decoder kernel ----------------
__global__ __launch_bounds__(NTH)
void decoder_kernel(const int*   __restrict__ y,
                    const float* __restrict__ gbi,
                    const float* __restrict__ gbh,
                    const float* __restrict__ out_b,
                    float* __restrict__ outp,
                    float* __restrict__ attnp)
{
    __shared__ __align__(16) float s_h  [NL][G][Hh];
    __shared__ __align__(16) float s_aw [G][Ld];
    __shared__ __align__(16) float s_app[G][Hh];
    __shared__ __align__(16) float s_x  [G][Hh];
    __shared__ __align__(16) float s_p2 [G][3][Hh];
    __shared__ __align__(16) float s_out[G][Vv][8];
    __shared__ float s_red[16 * G];
    __shared__ int   s_tok[G];

    const int tid  = threadIdx.x;
    const int jj   = tid & 255;
    const bool hi  = (tid >= 256);
    const int b0   = blockIdx.x * G;

    const __nv_bfloat16* Pattnh = g_pack + OFF_ATTNH;
    const __nv_bfloat16* Pcomba = g_pack + OFF_COMBA;
    const __nv_bfloat16* Pgih   = g_pack + OFF_GIH;
    const __nv_bfloat16* Pghh   = g_pack + OFF_GHH;
    const __nv_bfloat16* Pout   = g_pack + OFF_OUT;

    for (int i = tid; i < NL * G * Hh; i += NTH)
        (&s_h[0][0][0])[i] = 0.f;
    __syncthreads();

    for (int t = 0; t < Tt; t++) {
        // -------- token fetch --------
        if (tid < G)
            s_tok[tid] = (t == 0) ? 0 : y[(b0 + tid) * Tt + t - 1];
        __syncthreads();

        // -------- attention scores: h-part lo/hi K-halves; e-part from table --------
        {
            u64 acc[G] = {0, 0, 0, 0};
            const uint2* W = (const uint2*)Pattnh + (hi ? 32 * 256 : 0) + jj;
            const int kbase = hi ? 32 : 0;
            #pragma unroll 8
            for (int k4 = 0; k4 < 32; k4++) {
                uint2 wh = W[k4 * 256];
                u64 wx = cvt2(wh.x), wy = cvt2(wh.y);
                #pragma unroll
                for (int g = 0; g < G; g++) {
                    ulonglong2 xv = ((const ulonglong2*)(&s_h[0][g][0]))[kbase + k4];
                    fma2(acc[g], wx, xv.x);
                    fma2(acc[g], wy, xv.y);
                }
            }
            if (hi) {
                #pragma unroll
                for (int g = 0; g < G; g++) s_p2[g][0][jj] = sum2(acc[g]);
            }
            __syncthreads();

            float sc[G];
            #pragma unroll
            for (int g = 0; g < G; g++)
                sc[g] = hi ? -1e30f
                           : (sum2(acc[g]) + s_p2[g][0][jj] + g_Tattn[s_tok[g] * Ld + jj]);
            float m[G];
            #pragma unroll
            for (int g = 0; g < G; g++) m[g] = sc[g];
            block_reduce4(m, s_red, tid, true);
            float p[G];
            #pragma unroll
            for (int g = 0; g < G; g++) p[g] = hi ? 0.f : __expf(sc[g] - m[g]);
            float s[G];
            #pragma unroll
            for (int g = 0; g < G; g++) s[g] = p[g];
            block_reduce4(s, s_red, tid, false);
            if (!hi) {
                #pragma unroll
                for (int g = 0; g < G; g++) {
                    float a = p[g] * (1.f / s[g]);
                    s_aw[g][jj] = a;
                    attnp[((size_t)(b0 + g) * Tt + t) * Ld + jj] = a;
                }
            }
            __syncthreads();
        }

        // -------- applied = aw @ enc (transposed bf16 enc; thread owns h-pair) --------
        {
            const int g  = tid >> 7;                // batch row
            const int h2 = tid & 127;               // h pair {2h2, 2h2+1}
            const unsigned* ep =
                (const unsigned*)(g_encT + (size_t)(b0 + g) * Ld * Hh) + h2;
            const float4* awp = (const float4*)(s_aw[g]);
            u64 acc = 0;
            #pragma unroll
            for (int lb = 0; lb < 256; lb += 8) {
                unsigned e[8];
                #pragma unroll
                for (int u = 0; u < 8; u++) e[u] = ep[(lb + u) * 128];
                float4 a0 = awp[lb >> 2 ? (lb >> 2) : 0];   // awp[lb/4]
                float4 a1 = awp[(lb >> 2) + 1];
                a0 = awp[lb >> 2];
                fma2(acc, cvt2(e[0]), dup2(a0.x));
                fma2(acc, cvt2(e[1]), dup2(a0.y));
                fma2(acc, cvt2(e[2]), dup2(a0.z));
                fma2(acc, cvt2(e[3]), dup2(a0.w));
                fma2(acc, cvt2(e[4]), dup2(a1.x));
                fma2(acc, cvt2(e[5]), dup2(a1.y));
                fma2(acc, cvt2(e[6]), dup2(a1.z));
                fma2(acc, cvt2(e[7]), dup2(a1.w));
            }
            // acc lanes = applied[2h2], applied[2h2+1]
            ((float2*)&s_app[g][0])[h2] =
                make_float2(__uint_as_float((unsigned)acc),
                            __uint_as_float((unsigned)(acc >> 32)));
        }
        __syncthreads();

        // -------- combine: applied-part lo/hi K-halves; e-part from table --------
        {
            u64 acc[G] = {0, 0, 0, 0};
            const uint2* W = (const uint2*)Pcomba + (hi ? 32 * 256 : 0) + jj;
            const int kbase = hi ? 32 : 0;
            #pragma unroll 8
            for (int k4 = 0; k4 < 32; k4++) {
                uint2 wh = W[k4 * 256];
                u64 wx = cvt2(wh.x), wy = cvt2(wh.y);
                #pragma unroll
                for (int g = 0; g < G; g++) {
                    ulonglong2 xv = ((const ulonglong2*)(&s_app[g][0]))[kbase + k4];
                    fma2(acc[g], wx, xv.x);
                    fma2(acc[g], wy, xv.y);
                }
            }
            if (hi) {
                #pragma unroll
                for (int g = 0; g < G; g++) s_p2[g][0][jj] = sum2(acc[g]);
            }
            __syncthreads();
            if (!hi) {
                #pragma unroll
                for (int g = 0; g < G; g++)
                    s_x[g][jj] = fmaxf(sum2(acc[g]) + s_p2[g][0][jj]
                                       + g_Tcomb[s_tok[g] * Hh + jj], 0.f);
            }
            __syncthreads();
        }

        // -------- GRU layers: lo = ih, hi = hh; grouped weights (LDG.128+LDG.64) -----
        #pragma unroll
        for (int l = 0; l < NL; l++) {
            u64 a0[G] = {0,0,0,0}, a1[G] = {0,0,0,0}, a2[G] = {0,0,0,0};
            const __nv_bfloat16* Pg = (hi ? Pghh : Pgih) + l * 262144;
            const float* vb = hi ? &s_h[l][0][0] : &s_x[0][0];
            #pragma unroll 4
            for (int k4 = 0; k4 < 64; k4++) {
                int grp = k4 * 256 + jj;
                uint4 w01 = ((const uint4*)Pg)[grp * 2];
                uint2 w2  = ((const uint2*)Pg)[grp * 4 + 2];
                u64 w0x = cvt2(w01.x), w0y = cvt2(w01.y);
                u64 w1x = cvt2(w01.z), w1y = cvt2(w01.w);
                u64 w2x = cvt2(w2.x),  w2y = cvt2(w2.y);
                #pragma unroll
                for (int g = 0; g < G; g++) {
                    ulonglong2 xv = ((const ulonglong2*)(vb + g * Hh))[k4];
                    fma2(a0[g], w0x, xv.x); fma2(a0[g], w0y, xv.y);
                    fma2(a1[g], w1x, xv.x); fma2(a1[g], w1y, xv.y);
                    fma2(a2[g], w2x, xv.x); fma2(a2[g], w2y, xv.y);
                }
            }
            if (hi) {
                #pragma unroll
                for (int g = 0; g < G; g++) {
                    s_p2[g][0][jj] = sum2(a0[g]);
                    s_p2[g][1][jj] = sum2(a1[g]);
                    s_p2[g][2][jj] = sum2(a2[g]);
                }
            }
            __syncthreads();
            if (!hi) {
                const float bi0 = gbi[l * 768 + jj];
                const float bi1 = gbi[l * 768 + 256 + jj];
                const float bi2 = gbi[l * 768 + 512 + jj];
                const float bh0 = gbh[l * 768 + jj];
                const float bh1 = gbh[l * 768 + 256 + jj];
                const float bh2 = gbh[l * 768 + 512 + jj];
                #pragma unroll
                for (int g = 0; g < G; g++) {
                    float hprev = s_h[l][g][jj];
                    float i0 = sum2(a0[g]) + bi0, h0 = s_p2[g][0][jj] + bh0;
                    float i1 = sum2(a1[g]) + bi1, h1 = s_p2[g][1][jj] + bh1;
                    float i2 = sum2(a2[g]) + bi2, h2 = s_p2[g][2][jj] + bh2;
                    float r = 1.f / (1.f + __expf(-(i0 + h0)));
                    float z = 1.f / (1.f + __expf(-(i1 + h1)));
                    float n = tanhf(i2 + r * h2);
                    float hn = (1.f - z) * n + z * hprev;
                    s_h[l][g][jj] = hn;
                    s_x[g][jj]    = hn;
                }
            }
            __syncthreads();
        }

        // -------- output projection (K split 4 ways) + log_softmax --------
        {
            int j  = tid & 127;
            int sl = tid >> 7;
            u64 acc[G] = {0, 0, 0, 0};
            const uint2* W = (const uint2*)Pout + j;
            #pragma unroll 8
            for (int k4 = sl * 16; k4 < sl * 16 + 16; k4++) {
                uint2 wh = W[k4 * 128];
                u64 wx = cvt2(wh.x), wy = cvt2(wh.y);
                #pragma unroll
                for (int g = 0; g < G; g++) {
                    ulonglong2 hv = ((const ulonglong2*)s_x[g])[k4];
                    fma2(acc[g], wx, hv.x);
                    fma2(acc[g], wy, hv.y);
                }
            }
            float* s_op = &s_p2[0][0][0];
            #pragma unroll
            for (int g = 0; g < G; g++) s_op[(g * 4 + sl) * 128 + j] = sum2(acc[g]);
            __syncthreads();

            float oacc[G];
            #pragma unroll
            for (int g = 0; g < G; g++) {
                oacc[g] = (tid < 128)
                    ? (out_b[j] + s_op[(g * 4 + 0) * 128 + j] + s_op[(g * 4 + 1) * 128 + j]
                               + s_op[(g * 4 + 2) * 128 + j] + s_op[(g * 4 + 3) * 128 + j])
                    : -1e30f;
            }
            float m[G];
            #pragma unroll
            for (int g = 0; g < G; g++) m[g] = oacc[g];
            block_reduce4(m, s_red, tid, true);
            float p[G];
            #pragma unroll
            for (int g = 0; g < G; g++) p[g] = (tid < 128) ? __expf(oacc[g] - m[g]) : 0.f;
            float s[G];
            #pragma unroll
            for (int g = 0; g < G; g++) s[g] = p[g];
            block_reduce4(s, s_red, tid, false);
            if (tid < 128) {
                #pragma unroll
                for (int g = 0; g < G; g++)
                    s_out[g][j][t & 7] = oacc[g] - m[g] - logf(s[g]);
            }
        }

        // -------- flush staged outputs every 8 steps --------
        __syncthreads();
        if ((t & 7) == 7) {
            int g = tid >> 7, j = tid & 127;
            float4 v0 = *(float4*)&s_out[g][j][0];
            float4 v1 = *(float4*)&s_out[g][j][4];
            float4* dst = (float4*)(outp + ((size_t)(b0 + g) * Vv + j) * Tt + (t - 7));
            dst[0] = v0;
            dst[1] = v1;
            __syncthreads();
        }
    }
}

// ---------------- launch ----------------
extern "C" void kernel_launch(void* const* d_in, const int* in_sizes, int n_in,
                              void* d_out, int out_size)
{
    const float* x      = (const float*)d_in[0];
    const int*   y      = (const int*)  d_in[1];
    const float* emb    = (const float*)d_in[2];
    const float* attn_w = (const float*)d_in[3];
    const float* attn_b = (const float*)d_in[4];
    const float* comb_w = (const float*)d_in[5];
    const float* comb_b = (const float*)d_in[6];
    const float* gih    = (const float*)d_in[7];
    const float* ghh    = (const float*)d_in[8];
    const float* gbi    = (const float*)d_in[9];
    const float* gbh    = (const float*)d_in[10];
    const float* out_w  = (const float*)d_in[11];
    const float* out_b  = (const float*)d_in[12];

    float* outp  = (float*)d_out;                        // [B,V,T]
    float* attnp = (float*)d_out + (size_t)Bb * Vv * Tt; // [B,T,L]

    pack_all_kernel<<<PACK_BLOCKS + ENC_BLOCKS + TOK_BLOCKS, 256>>>(
        attn_w, comb_w, gih, ghh, out_w, x, emb, attn_b, comb_b);
    decoder_kernel<<<Bb / G, NTH>>>(y, gbi, gbh, out_b, outp, attnp);
}